// round 1
// baseline (speedup 1.0000x reference)
#include <cuda_runtime.h>

// Problem dims (fixed by the dataset's setup_inputs)
#define BB 2
#define DD 160
#define HH 192
#define WW 160
#define CZ 20                    // z-chunk depth per block
#define NCHUNK (DD / CZ)         // 8
#define BX 40                    // WW/4 quads per row
#define BY 4                     // rows per block
#define NTHREADS (BX * BY)       // 160
#define GY (HH / BY)             // 48
#define NBLK (GY * NCHUNK * BB)  // 768
#define NVOX ((double)BB * DD * HH * WW)

__device__ float g_partial[NBLK];

__device__ __forceinline__ float fsqrt_approx(float x) {
    float r;
    asm("sqrt.approx.f32 %0, %1;" : "=f"(r) : "f"(x));
    return r;
}

struct Row6 { float m, v0, v1, v2, v3, p; };

__device__ __forceinline__ Row6 load_row(const float* __restrict__ row, int x0, bool valid) {
    Row6 r;
    if (valid) {
        float4 v = *reinterpret_cast<const float4*>(row + x0);
        r.v0 = v.x; r.v1 = v.y; r.v2 = v.z; r.v3 = v.w;
        r.m = (x0 > 0)        ? row[x0 - 1] : 0.f;
        r.p = (x0 + 4 < WW)   ? row[x0 + 4] : 0.f;
    } else {
        r.m = r.v0 = r.v1 = r.v2 = r.v3 = r.p = 0.f;
    }
    return r;
}

struct ABC { float a0,a1,a2,a3, b0,b1,b2,b3, c0,c1,c2,c3; };

__device__ __forceinline__ void zero_abc(ABC& o) {
    o.a0=o.a1=o.a2=o.a3=0.f; o.b0=o.b1=o.b2=o.b3=0.f; o.c0=o.c1=o.c2=o.c3=0.f;
}

// Combine 3 rows (y-1, y, y+1) of one plane into per-lane partials:
//  a = smooth_x*smooth_y  (used for gz via z-diff)
//  b = diff_x  *smooth_y  (used for gx via z-smooth)
//  c = smooth_x*diff_y    (used for gy via z-smooth)
__device__ __forceinline__ void plane_abc(const Row6& r0, const Row6& r1, const Row6& r2, ABC& o) {
    float s0 = fmaf(2.f, r1.m , r0.m ) + r2.m ;
    float s1 = fmaf(2.f, r1.v0, r0.v0) + r2.v0;
    float s2 = fmaf(2.f, r1.v1, r0.v1) + r2.v1;
    float s3 = fmaf(2.f, r1.v2, r0.v2) + r2.v2;
    float s4 = fmaf(2.f, r1.v3, r0.v3) + r2.v3;
    float s5 = fmaf(2.f, r1.p , r0.p ) + r2.p ;
    float d0 = r2.m  - r0.m ;
    float d1 = r2.v0 - r0.v0;
    float d2 = r2.v1 - r0.v1;
    float d3 = r2.v2 - r0.v2;
    float d4 = r2.v3 - r0.v3;
    float d5 = r2.p  - r0.p ;
    o.a0 = fmaf(2.f, s1, s0) + s2;  o.b0 = s2 - s0;  o.c0 = fmaf(2.f, d1, d0) + d2;
    o.a1 = fmaf(2.f, s2, s1) + s3;  o.b1 = s3 - s1;  o.c1 = fmaf(2.f, d2, d1) + d3;
    o.a2 = fmaf(2.f, s3, s2) + s4;  o.b2 = s4 - s2;  o.c2 = fmaf(2.f, d3, d2) + d4;
    o.a3 = fmaf(2.f, s4, s3) + s5;  o.b3 = s5 - s3;  o.c3 = fmaf(2.f, d4, d3) + d5;
}

__device__ __forceinline__ float mag_lane(float bm2, float bm1, float bc,
                                          float cm2, float cm1, float cc,
                                          float am2, float ac) {
    float gx = fmaf(2.f, bm1, bm2) + bc;
    float gy = fmaf(2.f, cm1, cm2) + cc;
    float gz = ac - am2;
    return fsqrt_approx(fmaf(gx, gx, fmaf(gy, gy, fmaf(gz, gz, 1e-8f))));
}

__global__ __launch_bounds__(NTHREADS)
void sobel_loss_kernel(const float* __restrict__ pred, const float* __restrict__ targ) {
    const int tx = threadIdx.x;
    const int ty = threadIdx.y;
    const int x0 = tx * 4;
    const int y  = blockIdx.y * BY + ty;
    const int zb = blockIdx.z;                 // 0 .. BB*NCHUNK-1
    const int b  = zb / NCHUNK;
    const int zstart = (zb % NCHUNK) * CZ;

    const size_t batchOff = (size_t)b * DD * HH * WW;
    const float* __restrict__ P = pred + batchOff;
    const float* __restrict__ T = targ + batchOff;

    const bool y0ok = (y - 1) >= 0;
    const bool y2ok = (y + 1) < HH;

    ABC pm2, pm1, tm2, tm1;
    zero_abc(pm2); zero_abc(pm1); zero_abc(tm2); zero_abc(tm1);

    float acc = 0.f;

    #pragma unroll 3
    for (int i = 0; i < CZ + 2; ++i) {
        const int z = zstart - 1 + i;
        const bool zin = (z >= 0) && (z < DD);
        // offset computed in signed int; never dereferenced when !zin
        const int rowIdx = (z * HH + y) * WW;

        ABC pc, tc;
        {
            const float* pr = P + rowIdx;
            Row6 r0 = load_row(pr - WW, x0, zin && y0ok);
            Row6 r1 = load_row(pr,      x0, zin);
            Row6 r2 = load_row(pr + WW, x0, zin && y2ok);
            plane_abc(r0, r1, r2, pc);
        }
        {
            const float* tr = T + rowIdx;
            Row6 r0 = load_row(tr - WW, x0, zin && y0ok);
            Row6 r1 = load_row(tr,      x0, zin);
            Row6 r2 = load_row(tr + WW, x0, zin && y2ok);
            plane_abc(r0, r1, r2, tc);
        }

        if (i >= 2) {  // emit output at depth z-1
            float pg, tg;
            pg = mag_lane(pm2.b0, pm1.b0, pc.b0, pm2.c0, pm1.c0, pc.c0, pm2.a0, pc.a0);
            tg = mag_lane(tm2.b0, tm1.b0, tc.b0, tm2.c0, tm1.c0, tc.c0, tm2.a0, tc.a0);
            acc += fabsf(pg - tg);
            pg = mag_lane(pm2.b1, pm1.b1, pc.b1, pm2.c1, pm1.c1, pc.c1, pm2.a1, pc.a1);
            tg = mag_lane(tm2.b1, tm1.b1, tc.b1, tm2.c1, tm1.c1, tc.c1, tm2.a1, tc.a1);
            acc += fabsf(pg - tg);
            pg = mag_lane(pm2.b2, pm1.b2, pc.b2, pm2.c2, pm1.c2, pc.c2, pm2.a2, pc.a2);
            tg = mag_lane(tm2.b2, tm1.b2, tc.b2, tm2.c2, tm1.c2, tc.c2, tm2.a2, tc.a2);
            acc += fabsf(pg - tg);
            pg = mag_lane(pm2.b3, pm1.b3, pc.b3, pm2.c3, pm1.c3, pc.c3, pm2.a3, pc.a3);
            tg = mag_lane(tm2.b3, tm1.b3, tc.b3, tm2.c3, tm1.c3, tc.c3, tm2.a3, tc.a3);
            acc += fabsf(pg - tg);
        }

        pm2 = pm1; pm1 = pc;
        tm2 = tm1; tm1 = tc;
    }

    // deterministic block reduction (160 threads)
    __shared__ float red[NTHREADS];
    const int tid = ty * BX + tx;
    red[tid] = acc;
    __syncthreads();
    if (tid < 32) {
        float v = red[tid] + red[tid + 32] + red[tid + 64] + red[tid + 96] + red[tid + 128];
        #pragma unroll
        for (int o = 16; o > 0; o >>= 1)
            v += __shfl_down_sync(0xffffffffu, v, o);
        if (tid == 0)
            g_partial[blockIdx.z * GY + blockIdx.y] = v;
    }
}

__global__ __launch_bounds__(256)
void final_reduce_kernel(float* __restrict__ out) {
    __shared__ float red[256];
    float s = 0.f;
    for (int i = threadIdx.x; i < NBLK; i += 256)
        s += g_partial[i];
    red[threadIdx.x] = s;
    __syncthreads();
    #pragma unroll
    for (int stride = 128; stride >= 32; stride >>= 1) {
        if (threadIdx.x < stride) red[threadIdx.x] += red[threadIdx.x + stride];
        __syncthreads();
    }
    if (threadIdx.x < 32) {
        float v = red[threadIdx.x];
        #pragma unroll
        for (int o = 16; o > 0; o >>= 1)
            v += __shfl_down_sync(0xffffffffu, v, o);
        if (threadIdx.x == 0)
            out[0] = v * (float)(1.0 / NVOX);
    }
}

extern "C" void kernel_launch(void* const* d_in, const int* in_sizes, int n_in,
                              void* d_out, int out_size) {
    const float* pred = (const float*)d_in[0];
    const float* targ = (const float*)d_in[1];
    dim3 blk(BX, BY, 1);
    dim3 grd(1, GY, BB * NCHUNK);
    sobel_loss_kernel<<<grd, blk>>>(pred, targ);
    final_reduce_kernel<<<1, 256>>>((float*)d_out);
}

// round 2
// speedup vs baseline: 1.1966x; 1.1966x over previous
#include <cuda_runtime.h>

// Fixed problem dims
#define BB 2
#define DD 160
#define HH 192
#define WW 160
#define CZ 20                 // z-chunk depth; each block does 2 consecutive chunks
#define BX 40                 // WW/4 quads per row
#define BY 4                  // rows per block
#define NTHREADS (BX * BY)    // 160
#define GY (HH / BY)          // 48
#define GZ 8                  // 16 chunks total / 2 per block
#define NBLK (GY * GZ)        // 384
#define PLANE (HH * WW)
#define NVOX ((double)BB * DD * HH * WW)

typedef unsigned long long u64;

__device__ float g_partial[NBLK];
__device__ unsigned int g_count = 0;

// ---------- packed f32x2 helpers (sm_100+) ----------
__device__ __forceinline__ u64 pack2(float lo, float hi) {
    u64 r; asm("mov.b64 %0, {%1,%2};" : "=l"(r) : "f"(lo), "f"(hi)); return r;
}
__device__ __forceinline__ void unpack2(u64 v, float& lo, float& hi) {
    asm("mov.b64 {%0,%1}, %2;" : "=f"(lo), "=f"(hi) : "l"(v));
}
__device__ __forceinline__ u64 fma2(u64 a, u64 b, u64 c) {
    u64 d; asm("fma.rn.f32x2 %0, %1, %2, %3;" : "=l"(d) : "l"(a), "l"(b), "l"(c)); return d;
}
__device__ __forceinline__ u64 add2(u64 a, u64 b) {
    u64 d; asm("add.rn.f32x2 %0, %1, %2;" : "=l"(d) : "l"(a), "l"(b)); return d;
}
__device__ __forceinline__ u64 sub2(u64 a, u64 b) {
    u64 d; asm("sub.rn.f32x2 %0, %1, %2;" : "=l"(d) : "l"(a), "l"(b)); return d;
}
__device__ __forceinline__ float fsqrt_approx(float x) {
    float r; asm("sqrt.approx.f32 %0, %1;" : "=f"(r) : "f"(x)); return r;
}

// ---------- row / plane structures ----------
struct RowP { float m; u64 A, B; float p; };   // [x-1], (x0,x1), (x2,x3), [x+4]
struct ABCp { u64 aA, aB, bA, bB, cA, cB; };   // a=sx*sy, b=dx*sy, c=sx*dy

__device__ __forceinline__ RowP load_rowp(const float* __restrict__ p,
                                          bool valid, bool hasM, bool hasP) {
    RowP r;
    if (valid) {
        ulonglong2 q = __ldg(reinterpret_cast<const ulonglong2*>(p));
        r.A = q.x; r.B = q.y;
        r.m = hasM ? __ldg(p - 1) : 0.f;
        r.p = hasP ? __ldg(p + 4) : 0.f;
    } else {
        r.m = 0.f; r.A = 0ull; r.B = 0ull; r.p = 0.f;
    }
    return r;
}

// Combine rows y-1,y,y+1 of one plane into packed per-lane partials.
__device__ __forceinline__ ABCp plane_abc(const RowP& r0, const RowP& r1, const RowP& r2, u64 TWO2) {
    // y-direction (elementwise, fully packed)
    u64 sA = add2(fma2(TWO2, r1.A, r0.A), r2.A);
    u64 sB = add2(fma2(TWO2, r1.B, r0.B), r2.B);
    u64 dA = sub2(r2.A, r0.A);
    u64 dB = sub2(r2.B, r0.B);
    float sm = fmaf(2.f, r1.m, r0.m) + r2.m;
    float sp = fmaf(2.f, r1.p, r0.p) + r2.p;
    float dm = r2.m - r0.m;
    float dp = r2.p - r0.p;
    // x-direction: build shifted packets
    float s0, s1, s2, s3, d0, d1, d2, d3;
    unpack2(sA, s0, s1); unpack2(sB, s2, s3);
    unpack2(dA, d0, d1); unpack2(dB, d2, d3);
    u64 sL = pack2(sm, s0), sM = pack2(s1, s2), sR = pack2(s3, sp);
    u64 dL = pack2(dm, d0), dM = pack2(d1, d2), dR = pack2(d3, dp);
    ABCp o;
    o.aA = add2(fma2(TWO2, sA, sL), sM);
    o.aB = add2(fma2(TWO2, sB, sM), sR);
    o.bA = sub2(sM, sL);
    o.bB = sub2(sR, sM);
    o.cA = add2(fma2(TWO2, dA, dL), dM);
    o.cB = add2(fma2(TWO2, dB, dM), dR);
    return o;
}

// z-combine + magnitude for 4 lanes (packed up to the sqrt)
__device__ __forceinline__ void mag4(const ABCp& m2, const ABCp& m1, const ABCp& c,
                                     u64 TWO2, u64 EPS2, float out[4]) {
    u64 gxA = add2(fma2(TWO2, m1.bA, m2.bA), c.bA);
    u64 gxB = add2(fma2(TWO2, m1.bB, m2.bB), c.bB);
    u64 gyA = add2(fma2(TWO2, m1.cA, m2.cA), c.cA);
    u64 gyB = add2(fma2(TWO2, m1.cB, m2.cB), c.cB);
    u64 gzA = sub2(c.aA, m2.aA);
    u64 gzB = sub2(c.aB, m2.aB);
    u64 ssA = fma2(gxA, gxA, fma2(gyA, gyA, fma2(gzA, gzA, EPS2)));
    u64 ssB = fma2(gxB, gxB, fma2(gyB, gyB, fma2(gzB, gzB, EPS2)));
    float u0, u1, u2, u3;
    unpack2(ssA, u0, u1); unpack2(ssB, u2, u3);
    out[0] = fsqrt_approx(u0);
    out[1] = fsqrt_approx(u1);
    out[2] = fsqrt_approx(u2);
    out[3] = fsqrt_approx(u3);
}

__global__ __launch_bounds__(NTHREADS, 3)
void sobel_loss_fused(const float* __restrict__ pred, const float* __restrict__ targ,
                      float* __restrict__ out) {
    const int tx = threadIdx.x;
    const int ty = threadIdx.y;
    const int x0 = tx * 4;
    const int y  = blockIdx.y * BY + ty;
    const bool hasM = (tx > 0);
    const bool hasP = (tx < BX - 1);
    const bool y0ok = (y > 0);
    const bool y2ok = (y < HH - 1);

    const u64 TWO2 = pack2(2.f, 2.f);
    const u64 EPS2 = pack2(1e-8f, 1e-8f);

    float acc = 0.f;

    #pragma unroll 1
    for (int k = 0; k < 2; ++k) {
        const int cid = (blockIdx.z << 1) + k;      // 0..15
        const int b = cid >> 3;
        const int zstart = (cid & 7) * CZ;

        const float* Pp = pred + (size_t)b * DD * PLANE
                          + (ptrdiff_t)((zstart - 1) * HH + y) * WW + x0;
        const float* Tp = targ + (size_t)b * DD * PLANE
                          + (ptrdiff_t)((zstart - 1) * HH + y) * WW + x0;

        ABCp pm2, pm1, tm2, tm1;
        // warmup plane z = zstart-1 (may be out of volume)
        {
            const bool zv = (zstart > 0);
            pm2 = plane_abc(load_rowp(Pp - WW, zv && y0ok, hasM, hasP),
                            load_rowp(Pp,      zv,         hasM, hasP),
                            load_rowp(Pp + WW, zv && y2ok, hasM, hasP), TWO2);
            tm2 = plane_abc(load_rowp(Tp - WW, zv && y0ok, hasM, hasP),
                            load_rowp(Tp,      zv,         hasM, hasP),
                            load_rowp(Tp + WW, zv && y2ok, hasM, hasP), TWO2);
            Pp += PLANE; Tp += PLANE;
        }
        // warmup plane z = zstart (always in volume)
        {
            pm1 = plane_abc(load_rowp(Pp - WW, y0ok, hasM, hasP),
                            load_rowp(Pp,      true, hasM, hasP),
                            load_rowp(Pp + WW, y2ok, hasM, hasP), TWO2);
            tm1 = plane_abc(load_rowp(Tp - WW, y0ok, hasM, hasP),
                            load_rowp(Tp,      true, hasM, hasP),
                            load_rowp(Tp + WW, y2ok, hasM, hasP), TWO2);
            Pp += PLANE; Tp += PLANE;
        }
        // interior planes: z = zstart+1 .. zstart+CZ-1, always valid -> no z predicates
        #pragma unroll 2
        for (int j = 0; j < CZ - 1; ++j) {
            ABCp pc = plane_abc(load_rowp(Pp - WW, y0ok, hasM, hasP),
                                load_rowp(Pp,      true, hasM, hasP),
                                load_rowp(Pp + WW, y2ok, hasM, hasP), TWO2);
            ABCp tc = plane_abc(load_rowp(Tp - WW, y0ok, hasM, hasP),
                                load_rowp(Tp,      true, hasM, hasP),
                                load_rowp(Tp + WW, y2ok, hasM, hasP), TWO2);
            float pg[4], tg[4];
            mag4(pm2, pm1, pc, TWO2, EPS2, pg);
            mag4(tm2, tm1, tc, TWO2, EPS2, tg);
            acc += fabsf(pg[0] - tg[0]);
            acc += fabsf(pg[1] - tg[1]);
            acc += fabsf(pg[2] - tg[2]);
            acc += fabsf(pg[3] - tg[3]);
            pm2 = pm1; pm1 = pc; tm2 = tm1; tm1 = tc;
            Pp += PLANE; Tp += PLANE;
        }
        // final plane z = zstart+CZ (may be out of volume); emits z = zstart+CZ-1
        {
            const bool zv = (zstart + CZ < DD);
            ABCp pc = plane_abc(load_rowp(Pp - WW, zv && y0ok, hasM, hasP),
                                load_rowp(Pp,      zv,         hasM, hasP),
                                load_rowp(Pp + WW, zv && y2ok, hasM, hasP), TWO2);
            ABCp tc = plane_abc(load_rowp(Tp - WW, zv && y0ok, hasM, hasP),
                                load_rowp(Tp,      zv,         hasM, hasP),
                                load_rowp(Tp + WW, zv && y2ok, hasM, hasP), TWO2);
            float pg[4], tg[4];
            mag4(pm2, pm1, pc, TWO2, EPS2, pg);
            mag4(tm2, tm1, tc, TWO2, EPS2, tg);
            acc += fabsf(pg[0] - tg[0]);
            acc += fabsf(pg[1] - tg[1]);
            acc += fabsf(pg[2] - tg[2]);
            acc += fabsf(pg[3] - tg[3]);
        }
    }

    // ---------- block reduction (deterministic) ----------
    __shared__ float wsum[NTHREADS / 32];
    __shared__ int lastFlag;
    const int tid  = ty * BX + tx;
    const int wid  = tid >> 5;
    const int lane = tid & 31;

    float v = acc;
    #pragma unroll
    for (int o = 16; o > 0; o >>= 1)
        v += __shfl_down_sync(0xffffffffu, v, o);
    if (lane == 0) wsum[wid] = v;
    __syncthreads();

    if (tid == 0) {
        float s = wsum[0] + wsum[1] + wsum[2] + wsum[3] + wsum[4];
        g_partial[blockIdx.z * GY + blockIdx.y] = s;
        __threadfence();
        unsigned t = atomicAdd(&g_count, 1u);
        lastFlag = (t == NBLK - 1);
    }
    __syncthreads();

    // ---------- last block folds all partials (fixed order -> deterministic) ----------
    if (lastFlag) {
        const volatile float* gp = g_partial;
        float s = 0.f;
        for (int i = tid; i < NBLK; i += NTHREADS)
            s += gp[i];
        #pragma unroll
        for (int o = 16; o > 0; o >>= 1)
            s += __shfl_down_sync(0xffffffffu, s, o);
        if (lane == 0) wsum[wid] = s;
        __syncthreads();
        if (tid == 0) {
            float tot = wsum[0] + wsum[1] + wsum[2] + wsum[3] + wsum[4];
            out[0] = tot * (float)(1.0 / NVOX);
            g_count = 0;   // reset for next graph replay
        }
    }
}

extern "C" void kernel_launch(void* const* d_in, const int* in_sizes, int n_in,
                              void* d_out, int out_size) {
    const float* pred = (const float*)d_in[0];
    const float* targ = (const float*)d_in[1];
    dim3 blk(BX, BY, 1);
    dim3 grd(1, GY, GZ);
    sobel_loss_fused<<<grd, blk>>>(pred, targ, (float*)d_out);
}

// round 3
// speedup vs baseline: 1.3258x; 1.1079x over previous
#include <cuda_runtime.h>

// Fixed problem dims
#define BB 2
#define DD 160
#define HH 192
#define WW 160
#define CZ 20                 // z-chunk depth; each block does 2 consecutive chunks
#define NQ 40                 // WW/4 quads per row
#define BX (NQ * 2)           // 80: quad id = tx>>1, tensor select = tx&1
#define BY 4                  // rows per block
#define NTHREADS (BX * BY)    // 320
#define GY (HH / BY)          // 48
#define GZ 8                  // 16 chunks total / 2 per block
#define NBLK (GY * GZ)        // 384
#define PLANE (HH * WW)
#define NVOX ((double)BB * DD * HH * WW)

typedef unsigned long long u64;

__device__ float g_partial[NBLK];
__device__ unsigned int g_count = 0;

// ---------- packed f32x2 helpers (sm_100+) ----------
__device__ __forceinline__ u64 pack2(float lo, float hi) {
    u64 r; asm("mov.b64 %0, {%1,%2};" : "=l"(r) : "f"(lo), "f"(hi)); return r;
}
__device__ __forceinline__ void unpack2(u64 v, float& lo, float& hi) {
    asm("mov.b64 {%0,%1}, %2;" : "=f"(lo), "=f"(hi) : "l"(v));
}
__device__ __forceinline__ u64 fma2(u64 a, u64 b, u64 c) {
    u64 d; asm("fma.rn.f32x2 %0, %1, %2, %3;" : "=l"(d) : "l"(a), "l"(b), "l"(c)); return d;
}
__device__ __forceinline__ u64 add2(u64 a, u64 b) {
    u64 d; asm("add.rn.f32x2 %0, %1, %2;" : "=l"(d) : "l"(a), "l"(b)); return d;
}
__device__ __forceinline__ u64 sub2(u64 a, u64 b) {
    u64 d; asm("sub.rn.f32x2 %0, %1, %2;" : "=l"(d) : "l"(a), "l"(b)); return d;
}
__device__ __forceinline__ float fsqrt_approx(float x) {
    float r; asm("sqrt.approx.f32 %0, %1;" : "=f"(r) : "f"(x)); return r;
}

// ---------- row / plane structures ----------
struct RowP { float m; u64 A, B; float p; };   // [x-1], (x0,x1), (x2,x3), [x+4]
struct ABCp { u64 aA, aB, bA, bB, cA, cB; };   // a=sx*sy, b=dx*sy, c=sx*dy

__device__ __forceinline__ RowP load_rowp(const float* __restrict__ p,
                                          bool valid, bool hasM, bool hasP) {
    RowP r;
    if (valid) {
        ulonglong2 q = __ldg(reinterpret_cast<const ulonglong2*>(p));
        r.A = q.x; r.B = q.y;
        r.m = hasM ? __ldg(p - 1) : 0.f;
        r.p = hasP ? __ldg(p + 4) : 0.f;
    } else {
        r.m = 0.f; r.A = 0ull; r.B = 0ull; r.p = 0.f;
    }
    return r;
}

// Combine rows y-1,y,y+1 of one plane into packed per-lane partials.
__device__ __forceinline__ ABCp plane_abc(const RowP& r0, const RowP& r1, const RowP& r2, u64 TWO2) {
    u64 sA = add2(fma2(TWO2, r1.A, r0.A), r2.A);
    u64 sB = add2(fma2(TWO2, r1.B, r0.B), r2.B);
    u64 dA = sub2(r2.A, r0.A);
    u64 dB = sub2(r2.B, r0.B);
    float sm = fmaf(2.f, r1.m, r0.m) + r2.m;
    float sp = fmaf(2.f, r1.p, r0.p) + r2.p;
    float dm = r2.m - r0.m;
    float dp = r2.p - r0.p;
    float s0, s1, s2, s3, d0, d1, d2, d3;
    unpack2(sA, s0, s1); unpack2(sB, s2, s3);
    unpack2(dA, d0, d1); unpack2(dB, d2, d3);
    u64 sL = pack2(sm, s0), sM = pack2(s1, s2), sR = pack2(s3, sp);
    u64 dL = pack2(dm, d0), dM = pack2(d1, d2), dR = pack2(d3, dp);
    ABCp o;
    o.aA = add2(fma2(TWO2, sA, sL), sM);
    o.aB = add2(fma2(TWO2, sB, sM), sR);
    o.bA = sub2(sM, sL);
    o.bB = sub2(sR, sM);
    o.cA = add2(fma2(TWO2, dA, dL), dM);
    o.cB = add2(fma2(TWO2, dB, dM), dR);
    return o;
}

// z-combine + magnitude (this thread's tensor), exchange with partner lane,
// return contribution (even lane only, to avoid double counting).
__device__ __forceinline__ float emit4(const ABCp& m2, const ABCp& m1, const ABCp& c,
                                       u64 TWO2, u64 EPS2, int sel) {
    u64 gxA = add2(fma2(TWO2, m1.bA, m2.bA), c.bA);
    u64 gxB = add2(fma2(TWO2, m1.bB, m2.bB), c.bB);
    u64 gyA = add2(fma2(TWO2, m1.cA, m2.cA), c.cA);
    u64 gyB = add2(fma2(TWO2, m1.cB, m2.cB), c.cB);
    u64 gzA = sub2(c.aA, m2.aA);
    u64 gzB = sub2(c.aB, m2.aB);
    u64 ssA = fma2(gxA, gxA, fma2(gyA, gyA, fma2(gzA, gzA, EPS2)));
    u64 ssB = fma2(gxB, gxB, fma2(gyB, gyB, fma2(gzB, gzB, EPS2)));
    float u0, u1, u2, u3;
    unpack2(ssA, u0, u1); unpack2(ssB, u2, u3);
    float g0 = fsqrt_approx(u0);
    float g1 = fsqrt_approx(u1);
    float g2 = fsqrt_approx(u2);
    float g3 = fsqrt_approx(u3);
    float o0 = __shfl_xor_sync(0xffffffffu, g0, 1);
    float o1 = __shfl_xor_sync(0xffffffffu, g1, 1);
    float o2 = __shfl_xor_sync(0xffffffffu, g2, 1);
    float o3 = __shfl_xor_sync(0xffffffffu, g3, 1);
    float s = fabsf(g0 - o0) + fabsf(g1 - o1) + fabsf(g2 - o2) + fabsf(g3 - o3);
    return sel ? 0.f : s;
}

__global__ __launch_bounds__(NTHREADS, 3)
void sobel_loss_fused(const float* __restrict__ pred, const float* __restrict__ targ,
                      float* __restrict__ out) {
    const int tx   = threadIdx.x;
    const int ty   = threadIdx.y;
    const int quad = tx >> 1;
    const int sel  = tx & 1;                  // 0 = pred, 1 = target
    const int x0   = quad * 4;
    const int y    = blockIdx.y * BY + ty;
    const bool hasM = (quad > 0);
    const bool hasP = (quad < NQ - 1);
    const bool y0ok = (y > 0);
    const bool y2ok = (y < HH - 1);

    const float* __restrict__ src = sel ? targ : pred;

    const u64 TWO2 = pack2(2.f, 2.f);
    const u64 EPS2 = pack2(1e-8f, 1e-8f);

    float acc = 0.f;

    #pragma unroll 1
    for (int k = 0; k < 2; ++k) {
        const int cid = (blockIdx.z << 1) + k;      // 0..15
        const int b = cid >> 3;
        const int zstart = (cid & 7) * CZ;

        const float* Pp = src + (size_t)b * DD * PLANE
                          + (ptrdiff_t)((zstart - 1) * HH + y) * WW + x0;

        ABCp m2, m1;
        // warmup plane z = zstart-1 (may be out of volume)
        {
            const bool zv = (zstart > 0);
            m2 = plane_abc(load_rowp(Pp - WW, zv && y0ok, hasM, hasP),
                           load_rowp(Pp,      zv,         hasM, hasP),
                           load_rowp(Pp + WW, zv && y2ok, hasM, hasP), TWO2);
            Pp += PLANE;
        }
        // warmup plane z = zstart (always in volume)
        {
            m1 = plane_abc(load_rowp(Pp - WW, y0ok, hasM, hasP),
                           load_rowp(Pp,      true, hasM, hasP),
                           load_rowp(Pp + WW, y2ok, hasM, hasP), TWO2);
            Pp += PLANE;
        }
        // interior planes: z = zstart+1 .. zstart+CZ-1 (always valid, no z predicates)
        #pragma unroll 2
        for (int j = 0; j < CZ - 1; ++j) {
            ABCp c = plane_abc(load_rowp(Pp - WW, y0ok, hasM, hasP),
                               load_rowp(Pp,      true, hasM, hasP),
                               load_rowp(Pp + WW, y2ok, hasM, hasP), TWO2);
            acc += emit4(m2, m1, c, TWO2, EPS2, sel);
            m2 = m1; m1 = c;
            Pp += PLANE;
        }
        // final plane z = zstart+CZ (may be out of volume); emits z = zstart+CZ-1
        {
            const bool zv = (zstart + CZ < DD);
            ABCp c = plane_abc(load_rowp(Pp - WW, zv && y0ok, hasM, hasP),
                               load_rowp(Pp,      zv,         hasM, hasP),
                               load_rowp(Pp + WW, zv && y2ok, hasM, hasP), TWO2);
            acc += emit4(m2, m1, c, TWO2, EPS2, sel);
        }
    }

    // ---------- block reduction (deterministic) ----------
    __shared__ float wsum[NTHREADS / 32];
    __shared__ int lastFlag;
    const int tid  = ty * BX + tx;
    const int wid  = tid >> 5;
    const int lane = tid & 31;

    float v = acc;
    #pragma unroll
    for (int o = 16; o > 0; o >>= 1)
        v += __shfl_down_sync(0xffffffffu, v, o);
    if (lane == 0) wsum[wid] = v;
    __syncthreads();

    if (tid == 0) {
        float s = 0.f;
        #pragma unroll
        for (int w = 0; w < NTHREADS / 32; ++w) s += wsum[w];
        g_partial[blockIdx.z * GY + blockIdx.y] = s;
        __threadfence();
        unsigned t = atomicAdd(&g_count, 1u);
        lastFlag = (t == NBLK - 1);
    }
    __syncthreads();

    // ---------- last block folds all partials (fixed order -> deterministic) ----------
    if (lastFlag) {
        const volatile float* gp = g_partial;
        float s = 0.f;
        for (int i = tid; i < NBLK; i += NTHREADS)
            s += gp[i];
        #pragma unroll
        for (int o = 16; o > 0; o >>= 1)
            s += __shfl_down_sync(0xffffffffu, s, o);
        if (lane == 0) wsum[wid] = s;
        __syncthreads();
        if (tid == 0) {
            float tot = 0.f;
            #pragma unroll
            for (int w = 0; w < NTHREADS / 32; ++w) tot += wsum[w];
            out[0] = tot * (float)(1.0 / NVOX);
            g_count = 0;   // reset for next graph replay
        }
    }
}

extern "C" void kernel_launch(void* const* d_in, const int* in_sizes, int n_in,
                              void* d_out, int out_size) {
    const float* pred = (const float*)d_in[0];
    const float* targ = (const float*)d_in[1];
    dim3 blk(BX, BY, 1);
    dim3 grd(1, GY, GZ);
    sobel_loss_fused<<<grd, blk>>>(pred, targ, (float*)d_out);
}

// round 4
// speedup vs baseline: 1.4796x; 1.1160x over previous
#include <cuda_runtime.h>

// Fixed problem dims
#define BB 2
#define DD 160
#define HH 192
#define WW 160
#define CZ 20                 // z-chunk depth; each block does 2 consecutive chunks
#define NQ 40                 // WW/4 quads per row
#define BX (NQ * 2)           // 80: quad id = tx>>1, tensor select = tx&1
#define BY 4                  // rows per block
#define NTHREADS (BX * BY)    // 320
#define GY (HH / BY)          // 48
#define GZ 8                  // 16 chunks total / 2 per block
#define NBLK (GY * GZ)        // 384
#define PLANE (HH * WW)
#define NVOX ((double)BB * DD * HH * WW)
#define FULL 0xffffffffu

typedef unsigned long long u64;

__device__ float g_partial[NBLK];
__device__ unsigned int g_count = 0;

// ---------- packed f32x2 helpers (sm_100+) ----------
__device__ __forceinline__ u64 pack2(float lo, float hi) {
    u64 r; asm("mov.b64 %0, {%1,%2};" : "=l"(r) : "f"(lo), "f"(hi)); return r;
}
__device__ __forceinline__ void unpack2(u64 v, float& lo, float& hi) {
    asm("mov.b64 {%0,%1}, %2;" : "=f"(lo), "=f"(hi) : "l"(v));
}
__device__ __forceinline__ u64 fma2(u64 a, u64 b, u64 c) {
    u64 d; asm("fma.rn.f32x2 %0, %1, %2, %3;" : "=l"(d) : "l"(a), "l"(b), "l"(c)); return d;
}
__device__ __forceinline__ u64 add2(u64 a, u64 b) {
    u64 d; asm("add.rn.f32x2 %0, %1, %2;" : "=l"(d) : "l"(a), "l"(b)); return d;
}
__device__ __forceinline__ u64 sub2(u64 a, u64 b) {
    u64 d; asm("sub.rn.f32x2 %0, %1, %2;" : "=l"(d) : "l"(a), "l"(b)); return d;
}
__device__ __forceinline__ float fsqrt_approx(float x) {
    float r; asm("sqrt.approx.f32 %0, %1;" : "=f"(r) : "f"(x)); return r;
}

struct ABCp { u64 aA, aB, bA, bB, cA, cB; };   // a=sx*sy, b=dx*sy, c=sx*dy

struct Ctx {
    bool lftShfl, rgtShfl;   // x-halo available from lane +-2 via shuffle
    bool hasM, hasP;         // global x-boundary flags
};

// Build packed per-lane partials for one plane. p points at (y, x0) of plane z.
// v0/v1/v2 = validity of rows y-1 / y / y+1 (z and y bounds folded in).
__device__ __forceinline__ ABCp plane_abc(const float* __restrict__ p,
                                          bool v0, bool v1, bool v2,
                                          const Ctx cx, u64 TWO2) {
    u64 r0A = 0, r0B = 0, r1A = 0, r1B = 0, r2A = 0, r2B = 0;
    if (v0) { ulonglong2 q = __ldg(reinterpret_cast<const ulonglong2*>(p - WW)); r0A = q.x; r0B = q.y; }
    if (v1) { ulonglong2 q = __ldg(reinterpret_cast<const ulonglong2*>(p));      r1A = q.x; r1B = q.y; }
    if (v2) { ulonglong2 q = __ldg(reinterpret_cast<const ulonglong2*>(p + WW)); r2A = q.x; r2B = q.y; }

    // y-stage (elementwise on own quad)
    u64 sA = add2(fma2(TWO2, r1A, r0A), r2A);
    u64 sB = add2(fma2(TWO2, r1B, r0B), r2B);
    u64 dA = sub2(r2A, r0A);
    u64 dB = sub2(r2B, r0B);

    float s0, s1, s2, s3, d0, d1, d2, d3;
    unpack2(sA, s0, s1); unpack2(sB, s2, s3);
    unpack2(dA, d0, d1); unpack2(dB, d2, d3);

    // x-halo from neighbor lanes (same tensor = lane +- 2)
    float sm = __shfl_up_sync  (FULL, s3, 2);
    float dm = __shfl_up_sync  (FULL, d3, 2);
    float sp = __shfl_down_sync(FULL, s0, 2);
    float dp = __shfl_down_sync(FULL, d0, 2);

    // fallback for lanes whose neighbor is outside the warp / volume
    if (!cx.lftShfl) {
        float a = 0.f, b = 0.f, c = 0.f;
        if (cx.hasM) {
            if (v0) a = __ldg(p - WW - 1);
            if (v1) b = __ldg(p - 1);
            if (v2) c = __ldg(p + WW - 1);
        }
        sm = fmaf(2.f, b, a) + c;
        dm = c - a;
    }
    if (!cx.rgtShfl) {
        float a = 0.f, b = 0.f, c = 0.f;
        if (cx.hasP) {
            if (v0) a = __ldg(p - WW + 4);
            if (v1) b = __ldg(p + 4);
            if (v2) c = __ldg(p + WW + 4);
        }
        sp = fmaf(2.f, b, a) + c;
        dp = c - a;
    }

    // x-stage on shifted packets
    u64 sL = pack2(sm, s0), sM = pack2(s1, s2), sR = pack2(s3, sp);
    u64 dL = pack2(dm, d0), dM = pack2(d1, d2), dR = pack2(d3, dp);
    ABCp o;
    o.aA = add2(fma2(TWO2, sA, sL), sM);
    o.aB = add2(fma2(TWO2, sB, sM), sR);
    o.bA = sub2(sM, sL);
    o.bB = sub2(sR, sM);
    o.cA = add2(fma2(TWO2, dA, dL), dM);
    o.cB = add2(fma2(TWO2, dB, dM), dR);
    return o;
}

// z-combine + magnitude (this thread's tensor), exchange with partner lane,
// return contribution (even lane only, to avoid double counting).
__device__ __forceinline__ float emit4(const ABCp& m2, const ABCp& m1, const ABCp& c,
                                       u64 TWO2, u64 EPS2, int sel) {
    u64 gxA = add2(fma2(TWO2, m1.bA, m2.bA), c.bA);
    u64 gxB = add2(fma2(TWO2, m1.bB, m2.bB), c.bB);
    u64 gyA = add2(fma2(TWO2, m1.cA, m2.cA), c.cA);
    u64 gyB = add2(fma2(TWO2, m1.cB, m2.cB), c.cB);
    u64 gzA = sub2(c.aA, m2.aA);
    u64 gzB = sub2(c.aB, m2.aB);
    u64 ssA = fma2(gxA, gxA, fma2(gyA, gyA, fma2(gzA, gzA, EPS2)));
    u64 ssB = fma2(gxB, gxB, fma2(gyB, gyB, fma2(gzB, gzB, EPS2)));
    float u0, u1, u2, u3;
    unpack2(ssA, u0, u1); unpack2(ssB, u2, u3);
    float g0 = fsqrt_approx(u0);
    float g1 = fsqrt_approx(u1);
    float g2 = fsqrt_approx(u2);
    float g3 = fsqrt_approx(u3);
    float o0 = __shfl_xor_sync(FULL, g0, 1);
    float o1 = __shfl_xor_sync(FULL, g1, 1);
    float o2 = __shfl_xor_sync(FULL, g2, 1);
    float o3 = __shfl_xor_sync(FULL, g3, 1);
    float s = fabsf(g0 - o0) + fabsf(g1 - o1) + fabsf(g2 - o2) + fabsf(g3 - o3);
    return sel ? 0.f : s;
}

__global__ __launch_bounds__(NTHREADS, 3)
void sobel_loss_fused(const float* __restrict__ pred, const float* __restrict__ targ,
                      float* __restrict__ out) {
    const int tx   = threadIdx.x;
    const int ty   = threadIdx.y;
    const int quad = tx >> 1;
    const int sel  = tx & 1;                  // 0 = pred, 1 = target
    const int x0   = quad * 4;
    const int y    = blockIdx.y * BY + ty;
    const bool y0ok = (y > 0);
    const bool y2ok = (y < HH - 1);

    const float* __restrict__ src = sel ? targ : pred;

    const u64 TWO2 = pack2(2.f, 2.f);
    const u64 EPS2 = pack2(1e-8f, 1e-8f);

    // x-halo routing: is lane+-2 the same-row neighbor quad?
    Ctx cx;
    {
        const int key = (ty << 8) | quad;
        const int kUp = __shfl_up_sync  (FULL, key, 2);
        const int kDn = __shfl_down_sync(FULL, key, 2);
        cx.hasM = (quad > 0);
        cx.hasP = (quad < NQ - 1);
        cx.lftShfl = cx.hasM && (kUp == key - 1);
        cx.rgtShfl = cx.hasP && (kDn == key + 1);
    }

    float acc = 0.f;

    #pragma unroll 1
    for (int k = 0; k < 2; ++k) {
        const int cid = (blockIdx.z << 1) + k;      // 0..15
        const int b = cid >> 3;
        const int zstart = (cid & 7) * CZ;

        const float* Pp = src + (size_t)b * DD * PLANE
                          + (ptrdiff_t)((zstart - 1) * HH + y) * WW + x0;

        ABCp m2, m1;
        // warmup plane z = zstart-1 (may be out of volume)
        {
            const bool zv = (zstart > 0);
            m2 = plane_abc(Pp, zv && y0ok, zv, zv && y2ok, cx, TWO2);
            Pp += PLANE;
        }
        // warmup plane z = zstart (always in volume)
        {
            m1 = plane_abc(Pp, y0ok, true, y2ok, cx, TWO2);
            Pp += PLANE;
        }
        // interior planes: z = zstart+1 .. zstart+CZ-1 (always valid)
        #pragma unroll 2
        for (int j = 0; j < CZ - 1; ++j) {
            ABCp c = plane_abc(Pp, y0ok, true, y2ok, cx, TWO2);
            acc += emit4(m2, m1, c, TWO2, EPS2, sel);
            m2 = m1; m1 = c;
            Pp += PLANE;
        }
        // final plane z = zstart+CZ (may be out of volume); emits z = zstart+CZ-1
        {
            const bool zv = (zstart + CZ < DD);
            ABCp c = plane_abc(Pp, zv && y0ok, zv, zv && y2ok, cx, TWO2);
            acc += emit4(m2, m1, c, TWO2, EPS2, sel);
        }
    }

    // ---------- block reduction (deterministic) ----------
    __shared__ float wsum[NTHREADS / 32];
    __shared__ int lastFlag;
    const int tid  = ty * BX + tx;
    const int wid  = tid >> 5;
    const int lane = tid & 31;

    float v = acc;
    #pragma unroll
    for (int o = 16; o > 0; o >>= 1)
        v += __shfl_down_sync(FULL, v, o);
    if (lane == 0) wsum[wid] = v;
    __syncthreads();

    if (tid == 0) {
        float s = 0.f;
        #pragma unroll
        for (int w = 0; w < NTHREADS / 32; ++w) s += wsum[w];
        g_partial[blockIdx.z * GY + blockIdx.y] = s;
        __threadfence();
        unsigned t = atomicAdd(&g_count, 1u);
        lastFlag = (t == NBLK - 1);
    }
    __syncthreads();

    // ---------- last block folds all partials (fixed order -> deterministic) ----------
    if (lastFlag) {
        const volatile float* gp = g_partial;
        float s = 0.f;
        for (int i = tid; i < NBLK; i += NTHREADS)
            s += gp[i];
        #pragma unroll
        for (int o = 16; o > 0; o >>= 1)
            s += __shfl_down_sync(FULL, s, o);
        if (lane == 0) wsum[wid] = s;
        __syncthreads();
        if (tid == 0) {
            float tot = 0.f;
            #pragma unroll
            for (int w = 0; w < NTHREADS / 32; ++w) tot += wsum[w];
            out[0] = tot * (float)(1.0 / NVOX);
            g_count = 0;   // reset for next graph replay
        }
    }
}

extern "C" void kernel_launch(void* const* d_in, const int* in_sizes, int n_in,
                              void* d_out, int out_size) {
    const float* pred = (const float*)d_in[0];
    const float* targ = (const float*)d_in[1];
    dim3 blk(BX, BY, 1);
    dim3 grd(1, GY, GZ);
    sobel_loss_fused<<<grd, blk>>>(pred, targ, (float*)d_out);
}